// round 1
// baseline (speedup 1.0000x reference)
#include <cuda_runtime.h>
#include <math.h>

#define BB   8
#define NN   8192
#define SS   2048
#define C1c  128
#define C2c  256
#define CIN  384
#define TT   256
#define CO   256
#define COUNT_BN (BB*NN)

// ---------------- scratch (device globals: no runtime alloc allowed) ----------------
__device__ float d_p2t[BB*SS*C2c];                 // points2 transposed (B,S,C2) 16.8MB
__device__ int   d_idx3[BB*NN*3];
__device__ float d_w3[BB*NN*3];
__device__ float d_xin[(size_t)BB*CIN*NN];         // concat input (B,384,N) 100MB
__device__ float d_y1[(size_t)BB*CO*NN];           // layer1 raw output 64MB
__device__ float d_bias1[BB*CO];
__device__ float d_bias2[BB*CO];
__device__ float d_sum1[CO], d_sq1[CO], d_sum2[CO], d_sq2[CO];
__device__ float d_a1[CO], d_b1[CO], d_a2[CO], d_b2[CO];

__device__ __forceinline__ float gelu_exact(float x) {
    return 0.5f * x * (1.0f + erff(x * 0.7071067811865476f));
}

// ---------------- prep: fold t_embed conditioning into per-(b,o) biases; zero stats ----------------
__global__ void prep_kernel(const float* __restrict__ t_embed,
                            const float* __restrict__ w_t1, const float* __restrict__ b_t1,
                            const float* __restrict__ w_c1, const float* __restrict__ b_c1,
                            const float* __restrict__ w_t2, const float* __restrict__ b_t2,
                            const float* __restrict__ w_c2, const float* __restrict__ b_c2)
{
    int b = blockIdx.x;
    int t = threadIdx.x;                // 384 threads
    __shared__ float g[TT];
    __shared__ float te1[CIN];
    __shared__ float te2[CO];
    if (t < TT) g[t] = gelu_exact(t_embed[b*TT + t]);
    __syncthreads();
    {   // te1[c] = gelu(t) @ w_t1[c,:] + b_t1[c], c in [0,384)
        float s = b_t1[t];
        const float* w = w_t1 + (size_t)t*TT;
        #pragma unroll 8
        for (int k = 0; k < TT; k++) s = fmaf(g[k], w[k], s);
        te1[t] = s;
    }
    if (t < CO) {
        float s = b_t2[t];
        const float* w = w_t2 + (size_t)t*TT;
        #pragma unroll 8
        for (int k = 0; k < TT; k++) s = fmaf(g[k], w[k], s);
        te2[t] = s;
    }
    __syncthreads();
    if (t < CO) {
        float s1 = b_c1[t];
        const float* w1 = w_c1 + (size_t)t*CIN;
        #pragma unroll 8
        for (int k = 0; k < CIN; k++) s1 = fmaf(te1[k], w1[k], s1);
        d_bias1[b*CO + t] = s1;
        float s2 = b_c2[t];
        const float* w2 = w_c2 + (size_t)t*CO;
        #pragma unroll 8
        for (int k = 0; k < CO; k++) s2 = fmaf(te2[k], w2[k], s2);
        d_bias2[b*CO + t] = s2;
    }
    if (b == 0 && t < CO) {
        d_sum1[t] = 0.f; d_sq1[t] = 0.f; d_sum2[t] = 0.f; d_sq2[t] = 0.f;
    }
}

// ---------------- transpose points2 (B,C2,S) -> (B,S,C2) ----------------
__global__ void transpose_p2(const float* __restrict__ p2)
{
    __shared__ float tile[32][33];
    int b  = blockIdx.z;
    int s0 = blockIdx.x * 32;
    int c0 = blockIdx.y * 32;
    int tx = threadIdx.x, ty = threadIdx.y;   // 32 x 8
    const float* src = p2    + (size_t)b*C2c*SS;
    float*       dst = d_p2t + (size_t)b*SS*C2c;
    #pragma unroll
    for (int j = 0; j < 32; j += 8)
        tile[ty+j][tx] = src[(size_t)(c0+ty+j)*SS + s0 + tx];
    __syncthreads();
    #pragma unroll
    for (int j = 0; j < 32; j += 8)
        dst[(size_t)(s0+ty+j)*C2c + c0 + tx] = tile[tx][ty+j];
}

// ---------------- 3-NN: top-3 smallest d2 + normalized inverse-distance weights ----------------
__global__ void __launch_bounds__(256) top3_kernel(const float* __restrict__ xyz1,
                                                   const float* __restrict__ xyz2)
{
    __shared__ float sx[SS], sy[SS], sz[SS], sn[SS];
    int b = blockIdx.y;
    const float* x2 = xyz2 + (size_t)b*SS*3;
    for (int i = threadIdx.x; i < SS; i += 256) {
        float a = x2[i*3+0], bb = x2[i*3+1], c = x2[i*3+2];
        sx[i] = a; sy[i] = bb; sz[i] = c;
        sn[i] = a*a + bb*bb + c*c;
    }
    __syncthreads();
    int n = blockIdx.x * 256 + threadIdx.x;
    const float* p = xyz1 + ((size_t)b*NN + n)*3;
    float px = p[0], py = p[1], pz = p[2];
    float n1 = px*px + py*py + pz*pz;
    float d0 = 3.4e38f, d1 = 3.4e38f, d2 = 3.4e38f;
    int   i0 = 0, i1 = 0, i2 = 0;
    for (int s = 0; s < SS; s++) {
        float dot = px*sx[s] + py*sy[s] + pz*sz[s];
        float d = n1 + sn[s] - 2.0f*dot;   // same algebraic form as reference
        if (d < d2) {
            d2 = d; i2 = s;
            if (d2 < d1) {
                float td = d1; d1 = d2; d2 = td;
                int   ti = i1; i1 = i2; i2 = ti;
                if (d1 < d0) {
                    td = d0; d0 = d1; d1 = td;
                    ti = i0; i0 = i1; i1 = ti;
                }
            }
        }
    }
    float r0 = 1.f/(d0 + 1e-8f), r1 = 1.f/(d1 + 1e-8f), r2 = 1.f/(d2 + 1e-8f);
    float inv = 1.f/(r0 + r1 + r2);
    size_t base = ((size_t)b*NN + n)*3;
    d_idx3[base+0] = i0; d_idx3[base+1] = i1; d_idx3[base+2] = i2;
    d_w3[base+0] = r0*inv; d_w3[base+1] = r1*inv; d_w3[base+2] = r2*inv;
}

// ---------------- copy points1 into xin channels [0,128) ----------------
__global__ void copy_p1(const float* __restrict__ p1)
{
    int b = blockIdx.y;
    const float4* src = (const float4*)(p1   + (size_t)b*C1c*NN);
    float4*       dst = (float4*)(d_xin + (size_t)b*CIN*NN);
    int total = C1c*NN/4;
    for (int i = blockIdx.x*blockDim.x + threadIdx.x; i < total; i += gridDim.x*blockDim.x)
        dst[i] = src[i];
}

// ---------------- 3-NN interpolation into xin channels [128,384) ----------------
__global__ void __launch_bounds__(256) interp_kernel()
{
    __shared__ float sc[C2c][33];   // [channel][local n], padded
    __shared__ int   sidx[32*3];
    __shared__ float swt[32*3];
    int b  = blockIdx.y;
    int n0 = blockIdx.x * 32;
    int t  = threadIdx.x;           // 256 == C2
    if (t < 96) {
        size_t base = ((size_t)b*NN + n0)*3;
        sidx[t] = d_idx3[base + t];
        swt[t]  = d_w3[base + t];
    }
    __syncthreads();
    const float* p2t = d_p2t + (size_t)b*SS*C2c;
    #pragma unroll 4
    for (int nl = 0; nl < 32; nl++) {
        int   j0 = sidx[nl*3+0], j1 = sidx[nl*3+1], j2 = sidx[nl*3+2];
        float w0 = swt[nl*3+0],  w1 = swt[nl*3+1],  w2 = swt[nl*3+2];
        float v = w0 * p2t[(size_t)j0*C2c + t]
                + w1 * p2t[(size_t)j1*C2c + t]
                + w2 * p2t[(size_t)j2*C2c + t];
        sc[t][nl] = v;
    }
    __syncthreads();
    float* xout = d_xin + (size_t)b*CIN*NN + (size_t)C1c*NN + n0;
    int nl = t & 31;
    int c0 = t >> 5;                // 8 channels per pass
    #pragma unroll
    for (int c = c0; c < C2c; c += 8)
        xout[(size_t)c*NN + nl] = sc[c][nl];
}

// ---------------- SGEMM: Y[b] = A(256xK) @ X[b](KxN) + bias[b]  (+ channel stats) ----------------
// FUSEIN: apply y -> gelu(a_in[k]*y + b_in[k]) on B-operand load (BN1+GELU of layer1).
template<bool FUSEIN>
__global__ void __launch_bounds__(256) gemm_bn(const float* __restrict__ A,
                                               const float* __restrict__ X,
                                               float* __restrict__ Y,
                                               const float* __restrict__ bias,
                                               const float* __restrict__ ain,
                                               const float* __restrict__ bin,
                                               float* __restrict__ sumOut,
                                               float* __restrict__ sqOut,
                                               int K)
{
    __shared__ float As[8][132];
    __shared__ float Bs[8][128];
    int b  = blockIdx.z;
    int nT = blockIdx.x * 128;
    int oT = blockIdx.y * 128;
    int t  = threadIdx.x;
    int tx = t & 15, ty = t >> 4;
    const float* Xb = X + (size_t)b*K*NN;

    float acc[8][8];
    #pragma unroll
    for (int i = 0; i < 8; i++)
        #pragma unroll
        for (int j = 0; j < 8; j++) acc[i][j] = 0.f;

    for (int kT = 0; kT < K; kT += 8) {
        #pragma unroll
        for (int i = 0; i < 4; i++) {          // A tile 128(o) x 8(k)
            int e = t + i*256;
            int o = e >> 3, k = e & 7;
            As[k][o] = A[(size_t)(oT+o)*K + kT + k];
        }
        #pragma unroll
        for (int i = 0; i < 4; i++) {          // B tile 8(k) x 128(n)
            int e = t + i*256;
            int n = e & 127, k = e >> 7;
            float v = Xb[(size_t)(kT+k)*NN + nT + n];
            if (FUSEIN) {
                int kg = kT + k;
                v = gelu_exact(fmaf(ain[kg], v, bin[kg]));
            }
            Bs[k][n] = v;
        }
        __syncthreads();
        #pragma unroll
        for (int kk = 0; kk < 8; kk++) {
            float ar[8], br[8];
            #pragma unroll
            for (int i = 0; i < 8; i++) ar[i] = As[kk][ty + 16*i];
            #pragma unroll
            for (int j = 0; j < 8; j++) br[j] = Bs[kk][tx + 16*j];
            #pragma unroll
            for (int i = 0; i < 8; i++)
                #pragma unroll
                for (int j = 0; j < 8; j++)
                    acc[i][j] = fmaf(ar[i], br[j], acc[i][j]);
        }
        __syncthreads();
    }

    float* Yb = Y + (size_t)b*CO*NN;
    #pragma unroll
    for (int i = 0; i < 8; i++) {
        int o = oT + ty + 16*i;
        float bia = bias[b*CO + o];
        float s = 0.f, q = 0.f;
        #pragma unroll
        for (int j = 0; j < 8; j++) {
            int n = nT + tx + 16*j;
            float v = acc[i][j] + bia;
            Yb[(size_t)o*NN + n] = v;
            s += v; q = fmaf(v, v, q);
        }
        #pragma unroll
        for (int off = 8; off > 0; off >>= 1) {
            s += __shfl_down_sync(0xffffffffu, s, off, 16);
            q += __shfl_down_sync(0xffffffffu, q, off, 16);
        }
        if (tx == 0) {
            atomicAdd(&sumOut[o], s);
            atomicAdd(&sqOut[o], q);
        }
    }
}

// ---------------- BN scale/shift finalize ----------------
__global__ void bn_finalize(const float* __restrict__ sum, const float* __restrict__ sq,
                            const float* __restrict__ gamma, const float* __restrict__ beta,
                            float* __restrict__ aOut, float* __restrict__ bOut)
{
    int c = threadIdx.x;
    float m = sum[c] * (1.0f/COUNT_BN);
    float v = sq[c]  * (1.0f/COUNT_BN) - m*m;
    float inv = rsqrtf(v + 1e-5f);
    float a = gamma[c] * inv;
    aOut[c] = a;
    bOut[c] = beta[c] - a*m;
}

// ---------------- final: out = gelu(a2[c]*out + b2[c]) in place ----------------
__global__ void final_kernel(float* __restrict__ out)
{
    size_t i4 = (size_t)blockIdx.x * blockDim.x + threadIdx.x;
    size_t total4 = (size_t)BB*CO*NN/4;
    if (i4 >= total4) return;
    float4 v = ((float4*)out)[i4];
    size_t i = i4 * 4;
    int c = (int)((i / NN) % CO);
    float a = d_a2[c], bo = d_b2[c];
    v.x = gelu_exact(fmaf(a, v.x, bo));
    v.y = gelu_exact(fmaf(a, v.y, bo));
    v.z = gelu_exact(fmaf(a, v.z, bo));
    v.w = gelu_exact(fmaf(a, v.w, bo));
    ((float4*)out)[i4] = v;
}

// ---------------- launch ----------------
extern "C" void kernel_launch(void* const* d_in, const int* in_sizes, int n_in,
                              void* d_out, int out_size)
{
    const float* xyz1    = (const float*)d_in[0];
    const float* xyz2    = (const float*)d_in[1];
    const float* points1 = (const float*)d_in[2];
    const float* points2 = (const float*)d_in[3];
    const float* t_embed = (const float*)d_in[4];
    const float* w_t1 = (const float*)d_in[5];
    const float* b_t1 = (const float*)d_in[6];
    const float* w_c1 = (const float*)d_in[7];
    const float* b_c1 = (const float*)d_in[8];
    const float* g1   = (const float*)d_in[9];
    const float* be1  = (const float*)d_in[10];
    const float* w_t2 = (const float*)d_in[11];
    const float* b_t2 = (const float*)d_in[12];
    const float* w_c2 = (const float*)d_in[13];
    const float* b_c2 = (const float*)d_in[14];
    const float* g2   = (const float*)d_in[15];
    const float* be2  = (const float*)d_in[16];
    float* out = (float*)d_out;

    float *p_xin, *p_y1, *p_bias1, *p_bias2;
    float *p_sum1, *p_sq1, *p_sum2, *p_sq2, *p_a1, *p_b1, *p_a2, *p_b2;
    cudaGetSymbolAddress((void**)&p_xin,   d_xin);
    cudaGetSymbolAddress((void**)&p_y1,    d_y1);
    cudaGetSymbolAddress((void**)&p_bias1, d_bias1);
    cudaGetSymbolAddress((void**)&p_bias2, d_bias2);
    cudaGetSymbolAddress((void**)&p_sum1,  d_sum1);
    cudaGetSymbolAddress((void**)&p_sq1,   d_sq1);
    cudaGetSymbolAddress((void**)&p_sum2,  d_sum2);
    cudaGetSymbolAddress((void**)&p_sq2,   d_sq2);
    cudaGetSymbolAddress((void**)&p_a1,    d_a1);
    cudaGetSymbolAddress((void**)&p_b1,    d_b1);
    cudaGetSymbolAddress((void**)&p_a2,    d_a2);
    cudaGetSymbolAddress((void**)&p_b2,    d_b2);

    prep_kernel<<<BB, 384>>>(t_embed, w_t1, b_t1, w_c1, b_c1, w_t2, b_t2, w_c2, b_c2);
    transpose_p2<<<dim3(SS/32, C2c/32, BB), dim3(32, 8)>>>(points2);
    top3_kernel<<<dim3(NN/256, BB), 256>>>(xyz1, xyz2);
    copy_p1<<<dim3(256, BB), 256>>>(points1);
    interp_kernel<<<dim3(NN/32, BB), 256>>>();

    // Layer 1: y1 = w_c1 @ xin + bias1, accumulate stats
    gemm_bn<false><<<dim3(NN/128, 2, BB), 256>>>(w_c1, p_xin, p_y1, p_bias1,
                                                 nullptr, nullptr, p_sum1, p_sq1, CIN);
    bn_finalize<<<1, 256>>>(p_sum1, p_sq1, g1, be1, p_a1, p_b1);

    // Layer 2: y2 = w_c2 @ gelu(bn1(y1)) + bias2 -> d_out raw, accumulate stats
    gemm_bn<true><<<dim3(NN/128, 2, BB), 256>>>(w_c2, p_y1, out, p_bias2,
                                                p_a1, p_b1, p_sum2, p_sq2, CO);
    bn_finalize<<<1, 256>>>(p_sum2, p_sq2, g2, be2, p_a2, p_b2);

    final_kernel<<<(unsigned)((BB*CO*NN/4 + 255)/256), 256>>>(out);
}

// round 2
// speedup vs baseline: 1.8661x; 1.8661x over previous
#include <cuda_runtime.h>
#include <math.h>
#include <stdint.h>

#define BB   8
#define NN   8192
#define SS   2048
#define C1c  128
#define C2c  256
#define CIN  384
#define TT   256
#define CO   256
#define COUNT_BN (BB*NN)

// ---------------- scratch (device globals: no runtime alloc allowed) ----------------
__device__ float d_p2t[BB*SS*C2c];                 // points2 transposed (B,S,C2)
__device__ int   d_idx3[BB*NN*3];
__device__ float d_w3[BB*NN*3];
__device__ float d_itp[(size_t)BB*C2c*NN];         // interpolated channels (B,256,N)
__device__ float d_y1[(size_t)BB*CO*NN];           // layer1 raw output
__device__ float d_bias1[BB*CO];
__device__ float d_bias2[BB*CO];
__device__ float d_sum1[CO], d_sq1[CO], d_sum2[CO], d_sq2[CO];
__device__ float d_a1[CO], d_b1[CO], d_a2[CO], d_b2[CO];
// pre-permuted tf32 weights, fragment order: [m_tile][k_tile][4096]
__device__ uint32_t d_w1p[2*(CIN/32)*4096];
__device__ uint32_t d_w2p[2*(CO/32)*4096];

__device__ __forceinline__ float gelu_exact(float x) {
    return 0.5f * x * (1.0f + erff(x * 0.7071067811865476f));
}
__device__ __forceinline__ uint32_t to_tf32(float x) {
    uint32_t u;
    asm("cvt.rna.tf32.f32 %0, %1;" : "=r"(u) : "f"(x));
    return u;
}

// ---------------- prep: fold t_embed conditioning into per-(b,o) biases; zero stats ----------------
__global__ void prep_kernel(const float* __restrict__ t_embed,
                            const float* __restrict__ w_t1, const float* __restrict__ b_t1,
                            const float* __restrict__ w_c1, const float* __restrict__ b_c1,
                            const float* __restrict__ w_t2, const float* __restrict__ b_t2,
                            const float* __restrict__ w_c2, const float* __restrict__ b_c2)
{
    int b = blockIdx.x;
    int t = threadIdx.x;                // 384 threads
    __shared__ float g[TT];
    __shared__ float te1[CIN];
    __shared__ float te2[CO];
    if (t < TT) g[t] = gelu_exact(t_embed[b*TT + t]);
    __syncthreads();
    {
        float s = b_t1[t];
        const float* w = w_t1 + (size_t)t*TT;
        #pragma unroll 8
        for (int k = 0; k < TT; k++) s = fmaf(g[k], w[k], s);
        te1[t] = s;
    }
    if (t < CO) {
        float s = b_t2[t];
        const float* w = w_t2 + (size_t)t*TT;
        #pragma unroll 8
        for (int k = 0; k < TT; k++) s = fmaf(g[k], w[k], s);
        te2[t] = s;
    }
    __syncthreads();
    if (t < CO) {
        float s1 = b_c1[t];
        const float* w1 = w_c1 + (size_t)t*CIN;
        #pragma unroll 8
        for (int k = 0; k < CIN; k++) s1 = fmaf(te1[k], w1[k], s1);
        d_bias1[b*CO + t] = s1;
        float s2 = b_c2[t];
        const float* w2 = w_c2 + (size_t)t*CO;
        #pragma unroll 8
        for (int k = 0; k < CO; k++) s2 = fmaf(te2[k], w2[k], s2);
        d_bias2[b*CO + t] = s2;
    }
    if (b == 0 && t < CO) {
        d_sum1[t] = 0.f; d_sq1[t] = 0.f; d_sum2[t] = 0.f; d_sq2[t] = 0.f;
    }
}

// ---------------- permute weights into tf32 fragment order ----------------
// mma m16n8k8 A-fragment: a_reg = (r/8) + 2*(c/4), thread tt = (r%8)*4 + (c%4)
__global__ void permA_kernel(const float* __restrict__ w, uint32_t* __restrict__ dst, int K)
{
    int idx = blockIdx.x*256 + threadIdx.x;
    if (idx >= CO*K) return;
    int o = idx / K, k = idx % K;
    int mt = o >> 7, ml = o & 127;
    int ktile = k >> 5, kl = k & 31;
    int bm = ml >> 4, bk = kl >> 3;
    int r = ml & 15, c = kl & 7;
    int tt  = (r & 7)*4 + (c & 3);
    int reg = (r >> 3) + 2*(c >> 2);
    int KT = K >> 5;
    dst[(size_t)(mt*KT + ktile)*4096 + (bm*4 + bk)*128 + tt*4 + reg] = to_tf32(w[idx]);
}

// ---------------- transpose points2 (B,C2,S) -> (B,S,C2) ----------------
__global__ void transpose_p2(const float* __restrict__ p2)
{
    __shared__ float tile[32][33];
    int b  = blockIdx.z;
    int s0 = blockIdx.x * 32;
    int c0 = blockIdx.y * 32;
    int tx = threadIdx.x, ty = threadIdx.y;   // 32 x 8
    const float* src = p2    + (size_t)b*C2c*SS;
    float*       dst = d_p2t + (size_t)b*SS*C2c;
    #pragma unroll
    for (int j = 0; j < 32; j += 8)
        tile[ty+j][tx] = src[(size_t)(c0+ty+j)*SS + s0 + tx];
    __syncthreads();
    #pragma unroll
    for (int j = 0; j < 32; j += 8)
        dst[(size_t)(s0+ty+j)*C2c + c0 + tx] = tile[tx][ty+j];
}

// ---------------- 3-NN ----------------
__global__ void __launch_bounds__(256) top3_kernel(const float* __restrict__ xyz1,
                                                   const float* __restrict__ xyz2)
{
    __shared__ float sx[SS], sy[SS], sz[SS], sn[SS];
    int b = blockIdx.y;
    const float* x2 = xyz2 + (size_t)b*SS*3;
    for (int i = threadIdx.x; i < SS; i += 256) {
        float a = x2[i*3+0], bb = x2[i*3+1], c = x2[i*3+2];
        sx[i] = a; sy[i] = bb; sz[i] = c;
        sn[i] = a*a + bb*bb + c*c;
    }
    __syncthreads();
    int n = blockIdx.x * 256 + threadIdx.x;
    const float* p = xyz1 + ((size_t)b*NN + n)*3;
    float px = p[0], py = p[1], pz = p[2];
    float n1 = px*px + py*py + pz*pz;
    float d0 = 3.4e38f, d1 = 3.4e38f, d2 = 3.4e38f;
    int   i0 = 0, i1 = 0, i2 = 0;
    #pragma unroll 4
    for (int s = 0; s < SS; s++) {
        float dot = px*sx[s] + py*sy[s] + pz*sz[s];
        float d = n1 + sn[s] - 2.0f*dot;
        if (d < d2) {
            d2 = d; i2 = s;
            if (d2 < d1) {
                float td = d1; d1 = d2; d2 = td;
                int   ti = i1; i1 = i2; i2 = ti;
                if (d1 < d0) {
                    td = d0; d0 = d1; d1 = td;
                    ti = i0; i0 = i1; i1 = ti;
                }
            }
        }
    }
    float r0 = 1.f/(d0 + 1e-8f), r1 = 1.f/(d1 + 1e-8f), r2 = 1.f/(d2 + 1e-8f);
    float inv = 1.f/(r0 + r1 + r2);
    size_t base = ((size_t)b*NN + n)*3;
    d_idx3[base+0] = i0; d_idx3[base+1] = i1; d_idx3[base+2] = i2;
    d_w3[base+0] = r0*inv; d_w3[base+1] = r1*inv; d_w3[base+2] = r2*inv;
}

// ---------------- 3-NN interpolation into d_itp (B,256,N) ----------------
__global__ void __launch_bounds__(256) interp_kernel()
{
    __shared__ float sc[C2c][33];
    __shared__ int   sidx[32*3];
    __shared__ float swt[32*3];
    int b  = blockIdx.y;
    int n0 = blockIdx.x * 32;
    int t  = threadIdx.x;           // 256 == C2
    if (t < 96) {
        size_t base = ((size_t)b*NN + n0)*3;
        sidx[t] = d_idx3[base + t];
        swt[t]  = d_w3[base + t];
    }
    __syncthreads();
    const float* p2t = d_p2t + (size_t)b*SS*C2c;
    #pragma unroll 4
    for (int nl = 0; nl < 32; nl++) {
        int   j0 = sidx[nl*3+0], j1 = sidx[nl*3+1], j2 = sidx[nl*3+2];
        float w0 = swt[nl*3+0],  w1 = swt[nl*3+1],  w2 = swt[nl*3+2];
        float v = w0 * p2t[(size_t)j0*C2c + t]
                + w1 * p2t[(size_t)j1*C2c + t]
                + w2 * p2t[(size_t)j2*C2c + t];
        sc[t][nl] = v;
    }
    __syncthreads();
    float* xout = d_itp + (size_t)b*C2c*NN + n0;
    int nl = t & 31;
    int c0 = t >> 5;
    #pragma unroll
    for (int c = c0; c < C2c; c += 8)
        xout[(size_t)c*NN + nl] = sc[c][nl];
}

// ---------------- TF32 tensor-core GEMM: Y[b] = A(COxK) @ X[b](KxN) + bias[b] (+stats) ----------------
// Block tile 128(o) x 128(n) x 32(k). 8 warps: wm(2) x wn(4); warp tile 64x32.
// A pre-permuted in global (fragment order). B staged with bn-rotated pair swizzle.
#define MMA_TF32(d, a, bf)                                                        \
    asm volatile("mma.sync.aligned.m16n8k8.row.col.f32.tf32.tf32.f32 "            \
                 "{%0,%1,%2,%3}, {%4,%5,%6,%7}, {%8,%9}, {%0,%1,%2,%3};"          \
                 : "+f"(d[0]), "+f"(d[1]), "+f"(d[2]), "+f"(d[3])                 \
                 : "r"(a.x), "r"(a.y), "r"(a.z), "r"(a.w), "r"(bf.x), "r"(bf.y))

template<int KTOT, int C1B, bool FUSEIN>
__global__ void __launch_bounds__(256) gemm_tc(
    const uint32_t* __restrict__ Ap,
    const float* __restrict__ X0, size_t sx0,
    const float* __restrict__ X1, size_t sx1,
    float* __restrict__ Y,
    const float* __restrict__ bias,
    const float* __restrict__ ain, const float* __restrict__ bin,
    float* __restrict__ sumOut, float* __restrict__ sqOut)
{
    constexpr int NTILES = KTOT / 32;
    __shared__ __align__(16) uint32_t As[4096];
    __shared__ __align__(16) uint32_t Bs[4096];
    __shared__ float redS[128], redQ[128];

    int b = blockIdx.z, t = threadIdx.x;
    int lane = t & 31, w = t >> 5;
    int wm = w >> 2, wn = w & 3;
    int nT = blockIdx.x * 128, oT = blockIdx.y * 128;
    if (t < 128) { redS[t] = 0.f; redQ[t] = 0.f; }

    const uint32_t* ApT = Ap + (size_t)blockIdx.y * (NTILES*4096);

    float acc[4][4][4];
    #pragma unroll
    for (int i = 0; i < 4; i++)
        #pragma unroll
        for (int j = 0; j < 4; j++)
            #pragma unroll
            for (int r = 0; r < 4; r++) acc[i][j][r] = 0.f;

    uint4  pa[4];
    float4 pb[4];

    auto prefetch = [&](int kt) {
        int kT = kt * 32;
        const uint4* asrc = (const uint4*)(ApT + kt*4096);
        #pragma unroll
        for (int i = 0; i < 4; i++) pa[i] = asrc[i*256 + t];
        const float* base;
        if (kT < C1B) base = X0 + (size_t)b*sx0 + (size_t)kT*NN;
        else          base = X1 + (size_t)b*sx1 + (size_t)(kT - C1B)*NN;
        #pragma unroll
        for (int i = 0; i < 4; i++) {
            int kl = w + 8*i;
            pb[i] = *(const float4*)(base + (size_t)kl*NN + nT + lane*4);
        }
    };

    prefetch(0);

    for (int kt = 0; kt < NTILES; ++kt) {
        __syncthreads();   // previous compute done reading smem
        // ---- store A (linear, conflict-free) ----
        #pragma unroll
        for (int i = 0; i < 4; i++) ((uint4*)As)[i*256 + t] = pa[i];
        // ---- store B (fragment scatter, bn-rotated) ----
        int kT = kt * 32;
        #pragma unroll
        for (int i = 0; i < 4; i++) {
            int kl = w + 8*i;
            float4 v = pb[i];
            if (FUSEIN) {
                int kg = kT + kl;
                float a_ = ain[kg], b_ = bin[kg];
                v.x = gelu_exact(fmaf(a_, v.x, b_));
                v.y = gelu_exact(fmaf(a_, v.y, b_));
                v.z = gelu_exact(fmaf(a_, v.z, b_));
                v.w = gelu_exact(fmaf(a_, v.w, b_));
            }
            int bk  = kl >> 3;
            int reg = (kl >> 2) & 1;
            int k4  = kl & 3;
            int bn  = lane >> 1;
            int ttb = ((lane & 1) << 4) + k4;
            uint32_t bo = (uint32_t)((bk*16 + bn)*64 + reg);
            float vv0 = v.x, vv1 = v.y, vv2 = v.z, vv3 = v.w;
            Bs[bo + (((ttb + 0*4) + bn) & 31)*2] = to_tf32(vv0);
            Bs[bo + (((ttb + 1*4) + bn) & 31)*2] = to_tf32(vv1);
            Bs[bo + (((ttb + 2*4) + bn) & 31)*2] = to_tf32(vv2);
            Bs[bo + (((ttb + 3*4) + bn) & 31)*2] = to_tf32(vv3);
        }
        __syncthreads();
        if (kt + 1 < NTILES) prefetch(kt + 1);
        // ---- compute: 4 k8-steps ----
        #pragma unroll
        for (int bk = 0; bk < 4; ++bk) {
            uint4 av[4];
            #pragma unroll
            for (int mf = 0; mf < 4; ++mf)
                av[mf] = ((const uint4*)As)[((wm*4 + mf)*4 + bk)*32 + lane];
            uint2 bv[4];
            #pragma unroll
            for (int nf = 0; nf < 4; ++nf) {
                int bn = wn*4 + nf;
                bv[nf] = ((const uint2*)Bs)[(bk*16 + bn)*32 + ((lane + bn) & 31)];
            }
            #pragma unroll
            for (int mf = 0; mf < 4; ++mf)
                #pragma unroll
                for (int nf = 0; nf < 4; ++nf)
                    MMA_TF32(acc[mf][nf], av[mf], bv[nf]);
        }
    }

    // ---- epilogue: bias, store, stats ----
    float* Yb = Y + (size_t)b*CO*NN;
    #pragma unroll
    for (int mf = 0; mf < 4; ++mf) {
        int rl   = wm*64 + mf*16 + (lane >> 2);
        int o_lo = oT + rl;
        int o_hi = o_lo + 8;
        float bl = bias[b*CO + o_lo];
        float bh = bias[b*CO + o_hi];
        float sl = 0.f, ql = 0.f, sh = 0.f, qh = 0.f;
        #pragma unroll
        for (int nf = 0; nf < 4; ++nf) {
            int col = nT + wn*32 + nf*8 + ((lane & 3) << 1);
            float v0 = acc[mf][nf][0] + bl;
            float v1 = acc[mf][nf][1] + bl;
            float v2 = acc[mf][nf][2] + bh;
            float v3 = acc[mf][nf][3] + bh;
            float2 lo2; lo2.x = v0; lo2.y = v1;
            float2 hi2; hi2.x = v2; hi2.y = v3;
            *(float2*)(Yb + (size_t)o_lo*NN + col) = lo2;
            *(float2*)(Yb + (size_t)o_hi*NN + col) = hi2;
            sl += v0 + v1; ql += v0*v0 + v1*v1;
            sh += v2 + v3; qh += v2*v2 + v3*v3;
        }
        #pragma unroll
        for (int off = 1; off <= 2; off <<= 1) {
            sl += __shfl_xor_sync(0xffffffffu, sl, off);
            ql += __shfl_xor_sync(0xffffffffu, ql, off);
            sh += __shfl_xor_sync(0xffffffffu, sh, off);
            qh += __shfl_xor_sync(0xffffffffu, qh, off);
        }
        if ((lane & 3) == 0) {
            atomicAdd(&redS[rl],     sl);
            atomicAdd(&redQ[rl],     ql);
            atomicAdd(&redS[rl + 8], sh);
            atomicAdd(&redQ[rl + 8], qh);
        }
    }
    __syncthreads();
    if (t < 128) {
        atomicAdd(&sumOut[oT + t], redS[t]);
        atomicAdd(&sqOut[oT + t],  redQ[t]);
    }
}

// ---------------- BN scale/shift finalize ----------------
__global__ void bn_finalize(const float* __restrict__ sum, const float* __restrict__ sq,
                            const float* __restrict__ gamma, const float* __restrict__ beta,
                            float* __restrict__ aOut, float* __restrict__ bOut)
{
    int c = threadIdx.x;
    float m = sum[c] * (1.0f/COUNT_BN);
    float v = sq[c]  * (1.0f/COUNT_BN) - m*m;
    float inv = rsqrtf(v + 1e-5f);
    float a = gamma[c] * inv;
    aOut[c] = a;
    bOut[c] = beta[c] - a*m;
}

// ---------------- final: out = gelu(a2[c]*out + b2[c]) in place ----------------
__global__ void final_kernel(float* __restrict__ out)
{
    size_t i4 = (size_t)blockIdx.x * blockDim.x + threadIdx.x;
    size_t total4 = (size_t)BB*CO*NN/4;
    if (i4 >= total4) return;
    float4 v = ((float4*)out)[i4];
    size_t i = i4 * 4;
    int c = (int)((i / NN) % CO);
    float a = d_a2[c], bo = d_b2[c];
    v.x = gelu_exact(fmaf(a, v.x, bo));
    v.y = gelu_exact(fmaf(a, v.y, bo));
    v.z = gelu_exact(fmaf(a, v.z, bo));
    v.w = gelu_exact(fmaf(a, v.w, bo));
    ((float4*)out)[i4] = v;
}

// ---------------- launch ----------------
extern "C" void kernel_launch(void* const* d_in, const int* in_sizes, int n_in,
                              void* d_out, int out_size)
{
    const float* xyz1    = (const float*)d_in[0];
    const float* xyz2    = (const float*)d_in[1];
    const float* points1 = (const float*)d_in[2];
    const float* points2 = (const float*)d_in[3];
    const float* t_embed = (const float*)d_in[4];
    const float* w_t1 = (const float*)d_in[5];
    const float* b_t1 = (const float*)d_in[6];
    const float* w_c1 = (const float*)d_in[7];
    const float* b_c1 = (const float*)d_in[8];
    const float* g1   = (const float*)d_in[9];
    const float* be1  = (const float*)d_in[10];
    const float* w_t2 = (const float*)d_in[11];
    const float* b_t2 = (const float*)d_in[12];
    const float* w_c2 = (const float*)d_in[13];
    const float* b_c2 = (const float*)d_in[14];
    const float* g2   = (const float*)d_in[15];
    const float* be2  = (const float*)d_in[16];
    float* out = (float*)d_out;

    float *p_itp, *p_y1, *p_bias1, *p_bias2;
    float *p_sum1, *p_sq1, *p_sum2, *p_sq2, *p_a1, *p_b1, *p_a2, *p_b2;
    uint32_t *p_w1p, *p_w2p;
    cudaGetSymbolAddress((void**)&p_itp,   d_itp);
    cudaGetSymbolAddress((void**)&p_y1,    d_y1);
    cudaGetSymbolAddress((void**)&p_bias1, d_bias1);
    cudaGetSymbolAddress((void**)&p_bias2, d_bias2);
    cudaGetSymbolAddress((void**)&p_sum1,  d_sum1);
    cudaGetSymbolAddress((void**)&p_sq1,   d_sq1);
    cudaGetSymbolAddress((void**)&p_sum2,  d_sum2);
    cudaGetSymbolAddress((void**)&p_sq2,   d_sq2);
    cudaGetSymbolAddress((void**)&p_a1,    d_a1);
    cudaGetSymbolAddress((void**)&p_b1,    d_b1);
    cudaGetSymbolAddress((void**)&p_a2,    d_a2);
    cudaGetSymbolAddress((void**)&p_b2,    d_b2);
    cudaGetSymbolAddress((void**)&p_w1p,   d_w1p);
    cudaGetSymbolAddress((void**)&p_w2p,   d_w2p);

    prep_kernel<<<BB, 384>>>(t_embed, w_t1, b_t1, w_c1, b_c1, w_t2, b_t2, w_c2, b_c2);
    permA_kernel<<<(CO*CIN + 255)/256, 256>>>(w_c1, p_w1p, CIN);
    permA_kernel<<<(CO*CO  + 255)/256, 256>>>(w_c2, p_w2p, CO);
    transpose_p2<<<dim3(SS/32, C2c/32, BB), dim3(32, 8)>>>(points2);
    top3_kernel<<<dim3(NN/256, BB), 256>>>(xyz1, xyz2);
    interp_kernel<<<dim3(NN/32, BB), 256>>>();

    // Layer 1: y1 = w_c1 @ [points1; itp] + bias1, accumulate stats
    gemm_tc<CIN, C1c, false><<<dim3(NN/128, 2, BB), 256>>>(
        p_w1p, points1, (size_t)C1c*NN, p_itp, (size_t)C2c*NN,
        p_y1, p_bias1, nullptr, nullptr, p_sum1, p_sq1);
    bn_finalize<<<1, 256>>>(p_sum1, p_sq1, g1, be1, p_a1, p_b1);

    // Layer 2: out_raw = w_c2 @ gelu(bn1(y1)) + bias2, accumulate stats
    gemm_tc<CO, CO, true><<<dim3(NN/128, 2, BB), 256>>>(
        p_w2p, p_y1, (size_t)CO*NN, p_y1, (size_t)CO*NN,
        out, p_bias2, p_a1, p_b1, p_sum2, p_sq2);
    bn_finalize<<<1, 256>>>(p_sum2, p_sq2, g2, be2, p_a2, p_b2);

    final_kernel<<<(unsigned)((BB*CO*NN/4 + 255)/256), 256>>>(out);
}

// round 4
// speedup vs baseline: 2.2305x; 1.1953x over previous
#include <cuda_runtime.h>
#include <cuda_fp16.h>
#include <math.h>
#include <stdint.h>

#define BB   8
#define NN   8192
#define SS   2048
#define C1c  128
#define C2c  256
#define CIN  384
#define TT   256
#define CO   256
#define COUNT_BN (BB*NN)

// ---------------- scratch (device globals) ----------------
__device__ float  d_p2t[BB*SS*C2c];
__device__ int    d_idx3[BB*NN*3];
__device__ float  d_w3[BB*NN*3];
__device__ float  d_itp[(size_t)BB*C2c*NN];
__device__ __half d_y1h[(size_t)BB*CO*NN];          // layer1 output, fp16
__device__ float  d_bias1[BB*CO];
__device__ float  d_bias2[BB*CO];
__device__ float  d_sum1[CO], d_sq1[CO], d_sum2[CO], d_sq2[CO];
__device__ float  d_a1[CO], d_b1[CO], d_a2[CO], d_b2[CO];
// fp16 A images in m16n8k16 fragment order: [ktile][bm(16)][bk(2)][lane(32)][reg(4)] uint32
__device__ __half d_w1img[CO*CIN];
__device__ __half d_w2img[CO*CO];

__device__ __forceinline__ float gelu_exact(float x) {
    return 0.5f * x * (1.0f + erff(x * 0.7071067811865476f));
}
__device__ __forceinline__ uint32_t smem_u32(const void* p) {
    uint32_t a;
    asm("{ .reg .u64 tmp; cvta.to.shared.u64 tmp, %1; cvt.u32.u64 %0, tmp; }" : "=r"(a) : "l"(p));
    return a;
}
__device__ __forceinline__ void cp16(uint32_t dst, const void* src) {
    asm volatile("cp.async.cg.shared.global [%0], [%1], 16;" :: "r"(dst), "l"(src));
}
__device__ __forceinline__ void cp_commit() { asm volatile("cp.async.commit_group;" ::: "memory"); }
__device__ __forceinline__ void cp_wait0()  { asm volatile("cp.async.wait_group 0;" ::: "memory"); }

#define MMA_F16(d, a, b0, b1)                                                     \
    asm volatile("mma.sync.aligned.m16n8k16.row.col.f32.f16.f16.f32 "             \
                 "{%0,%1,%2,%3}, {%4,%5,%6,%7}, {%8,%9}, {%0,%1,%2,%3};"          \
                 : "+f"(d[0]), "+f"(d[1]), "+f"(d[2]), "+f"(d[3])                 \
                 : "r"(a.x), "r"(a.y), "r"(a.z), "r"(a.w), "r"(b0), "r"(b1))

// ---------------- prep: fold t_embed conditioning into per-(b,o) biases ----------------
__global__ void prep_kernel(const float* __restrict__ t_embed,
                            const float* __restrict__ w_t1, const float* __restrict__ b_t1,
                            const float* __restrict__ w_c1, const float* __restrict__ b_c1,
                            const float* __restrict__ w_t2, const float* __restrict__ b_t2,
                            const float* __restrict__ w_c2, const float* __restrict__ b_c2)
{
    int b = blockIdx.x;
    int t = threadIdx.x;                // 384 threads
    __shared__ float g[TT];
    __shared__ float te1[CIN];
    __shared__ float te2[CO];
    if (t < TT) g[t] = gelu_exact(t_embed[b*TT + t]);
    __syncthreads();
    {
        float s = b_t1[t];
        const float* w = w_t1 + (size_t)t*TT;
        #pragma unroll 8
        for (int k = 0; k < TT; k++) s = fmaf(g[k], w[k], s);
        te1[t] = s;
    }
    if (t < CO) {
        float s = b_t2[t];
        const float* w = w_t2 + (size_t)t*TT;
        #pragma unroll 8
        for (int k = 0; k < TT; k++) s = fmaf(g[k], w[k], s);
        te2[t] = s;
    }
    __syncthreads();
    if (t < CO) {
        float s1 = b_c1[t];
        const float* w1 = w_c1 + (size_t)t*CIN;
        #pragma unroll 8
        for (int k = 0; k < CIN; k++) s1 = fmaf(te1[k], w1[k], s1);
        d_bias1[b*CO + t] = s1;
        float s2 = b_c2[t];
        const float* w2 = w_c2 + (size_t)t*CO;
        #pragma unroll 8
        for (int k = 0; k < CO; k++) s2 = fmaf(te2[k], w2[k], s2);
        d_bias2[b*CO + t] = s2;
    }
    if (b == 0 && t < CO) {
        d_sum1[t] = 0.f; d_sq1[t] = 0.f; d_sum2[t] = 0.f; d_sq2[t] = 0.f;
    }
}

// ---------------- permute weights into fp16 m16n8k16 fragment order ----------------
// a0={A[g][2t],A[g][2t+1]}, a1=rows+8, a2=k+8, a3=both; lane=g*4+t; reg=hi+2*khi
__global__ void permA16(const float* __restrict__ w, __half* __restrict__ img, int K)
{
    int idx = blockIdx.x*256 + threadIdx.x;
    if (idx >= CO*K) return;
    int o = idx / K, k = idx % K;
    int bm = o >> 4, r = o & 15;
    int g = r & 7, hi = r >> 3;
    int kt = k >> 5, kl = k & 31;
    int bk = kl >> 4, kk = kl & 15;
    int tq  = (kk & 7) >> 1;
    int khi = kk >> 3;
    int klo = kk & 1;
    int lane = g*4 + tq;
    int reg  = hi + 2*khi;
    size_t uidx = ((size_t)(kt*16 + bm)*2 + bk)*128 + lane*4 + reg;
    img[uidx*2 + klo] = __float2half_rn(w[idx]);
}

// ---------------- transpose points2 (B,C2,S) -> (B,S,C2) ----------------
__global__ void transpose_p2(const float* __restrict__ p2)
{
    __shared__ float tile[32][33];
    int b  = blockIdx.z;
    int s0 = blockIdx.x * 32;
    int c0 = blockIdx.y * 32;
    int tx = threadIdx.x, ty = threadIdx.y;
    const float* src = p2    + (size_t)b*C2c*SS;
    float*       dst = d_p2t + (size_t)b*SS*C2c;
    #pragma unroll
    for (int j = 0; j < 32; j += 8)
        tile[ty+j][tx] = src[(size_t)(c0+ty+j)*SS + s0 + tx];
    __syncthreads();
    #pragma unroll
    for (int j = 0; j < 32; j += 8)
        dst[(size_t)(s0+ty+j)*C2c + c0 + tx] = tile[tx][ty+j];
}

// ---------------- 3-NN ----------------
__global__ void __launch_bounds__(256) top3_kernel(const float* __restrict__ xyz1,
                                                   const float* __restrict__ xyz2)
{
    __shared__ float sx[SS], sy[SS], sz[SS], sn[SS];
    int b = blockIdx.y;
    const float* x2 = xyz2 + (size_t)b*SS*3;
    for (int i = threadIdx.x; i < SS; i += 256) {
        float a = x2[i*3+0], bb = x2[i*3+1], c = x2[i*3+2];
        sx[i] = a; sy[i] = bb; sz[i] = c;
        sn[i] = a*a + bb*bb + c*c;
    }
    __syncthreads();
    int n = blockIdx.x * 256 + threadIdx.x;
    const float* p = xyz1 + ((size_t)b*NN + n)*3;
    float px = p[0], py = p[1], pz = p[2];
    float n1 = px*px + py*py + pz*pz;
    float d0 = 3.4e38f, d1 = 3.4e38f, d2 = 3.4e38f;
    int   i0 = 0, i1 = 0, i2 = 0;
    #pragma unroll 4
    for (int s = 0; s < SS; s++) {
        float dot = px*sx[s] + py*sy[s] + pz*sz[s];
        float d = n1 + sn[s] - 2.0f*dot;
        if (d < d2) {
            d2 = d; i2 = s;
            if (d2 < d1) {
                float td = d1; d1 = d2; d2 = td;
                int   ti = i1; i1 = i2; i2 = ti;
                if (d1 < d0) {
                    td = d0; d0 = d1; d1 = td;
                    ti = i0; i0 = i1; i1 = ti;
                }
            }
        }
    }
    float r0 = 1.f/(d0 + 1e-8f), r1 = 1.f/(d1 + 1e-8f), r2 = 1.f/(d2 + 1e-8f);
    float inv = 1.f/(r0 + r1 + r2);
    size_t base = ((size_t)b*NN + n)*3;
    d_idx3[base+0] = i0; d_idx3[base+1] = i1; d_idx3[base+2] = i2;
    d_w3[base+0] = r0*inv; d_w3[base+1] = r1*inv; d_w3[base+2] = r2*inv;
}

// ---------------- 3-NN interpolation into d_itp (B,256,N) ----------------
__global__ void __launch_bounds__(256) interp_kernel()
{
    __shared__ float sc[C2c][33];
    __shared__ int   sidx[32*3];
    __shared__ float swt[32*3];
    int b  = blockIdx.y;
    int n0 = blockIdx.x * 32;
    int t  = threadIdx.x;
    if (t < 96) {
        size_t base = ((size_t)b*NN + n0)*3;
        sidx[t] = d_idx3[base + t];
        swt[t]  = d_w3[base + t];
    }
    __syncthreads();
    const float* p2t = d_p2t + (size_t)b*SS*C2c;
    #pragma unroll 4
    for (int nl = 0; nl < 32; nl++) {
        int   j0 = sidx[nl*3+0], j1 = sidx[nl*3+1], j2 = sidx[nl*3+2];
        float w0 = swt[nl*3+0],  w1 = swt[nl*3+1],  w2 = swt[nl*3+2];
        float v = w0 * p2t[(size_t)j0*C2c + t]
                + w1 * p2t[(size_t)j1*C2c + t]
                + w2 * p2t[(size_t)j2*C2c + t];
        sc[t][nl] = v;
    }
    __syncthreads();
    float* xout = d_itp + (size_t)b*C2c*NN + n0;
    int nl = t & 31;
    int c0 = t >> 5;
    #pragma unroll
    for (int c = c0; c < C2c; c += 8)
        xout[(size_t)c*NN + nl] = sc[c][nl];
}

// ---------------- fp16 tensor-core GEMM ----------------
// Block tile M=256(all CO) x N=64, K chunked by 32. 8 warps: wm(4) x wn(2); warp 64x32.
// A: cp.async from prebuilt fragment image (linear). B: LDG -> (bn-gelu) -> half2 STS (swizzled).
// Bs[kp][n] holds half2 {x[2kp,n], x[2kp+1,n]}; word = kp*64 + (n ^ ((kp&3)<<3)).
template<int KTOT, bool FUSEIN, bool SRCH, bool OUTH>
__global__ void __launch_bounds__(256) gemm_f16(
    const __half* __restrict__ AimgH,
    const float* __restrict__ X0, size_t sx0,
    const float* __restrict__ X1, size_t sx1, int C1B,
    const __half* __restrict__ Xh,
    float* __restrict__ Yf, __half* __restrict__ Yh,
    const float* __restrict__ bias,
    const float* __restrict__ ain, const float* __restrict__ bin,
    float* __restrict__ sumOut, float* __restrict__ sqOut)
{
    constexpr int NC = KTOT / 32;
    __shared__ __align__(16) uint4    As[2][1024];   // 16KB per buffer
    __shared__ __align__(16) uint32_t Bs[2][1024];   // 4KB per buffer
    __shared__ float redS[CO], redQ[CO];

    const uint32_t* Aimg = (const uint32_t*)AimgH;
    int t = threadIdx.x, l = t & 31, w = t >> 5;
    int wm = w >> 1, wn = w & 1;
    int g = l >> 2, tq = l & 3;
    int b = blockIdx.y, nT = blockIdx.x * 64;

    redS[t] = 0.f; redQ[t] = 0.f;

    int kp = t >> 4, n4 = t & 15;    // staging task: k-pair row, n quad

    float acc[4][4][4];
    #pragma unroll
    for (int i = 0; i < 4; i++)
        #pragma unroll
        for (int j = 0; j < 4; j++)
            #pragma unroll
            for (int r = 0; r < 4; r++) acc[i][j][r] = 0.f;

    float pv[8];
    auto stageB = [&](int c) {
        int k0 = c*32 + 2*kp;
        if (SRCH) {
            const __half* bh = Xh + (size_t)b*CO*NN + (size_t)k0*NN + nT + 4*n4;
            uint2 u0 = *(const uint2*)bh;
            uint2 u1 = *(const uint2*)(bh + NN);
            __half2 h;
            h = *(__half2*)&u0.x; pv[0] = __low2float(h); pv[1] = __high2float(h);
            h = *(__half2*)&u0.y; pv[2] = __low2float(h); pv[3] = __high2float(h);
            h = *(__half2*)&u1.x; pv[4] = __low2float(h); pv[5] = __high2float(h);
            h = *(__half2*)&u1.y; pv[6] = __low2float(h); pv[7] = __high2float(h);
        } else {
            const float* base = (k0 < C1B)
                ? X0 + (size_t)b*sx0 + (size_t)k0*NN
                : X1 + (size_t)b*sx1 + (size_t)(k0 - C1B)*NN;
            float4 v0 = *(const float4*)(base + nT + 4*n4);
            float4 v1 = *(const float4*)(base + NN + nT + 4*n4);
            pv[0] = v0.x; pv[1] = v0.y; pv[2] = v0.z; pv[3] = v0.w;
            pv[4] = v1.x; pv[5] = v1.y; pv[6] = v1.z; pv[7] = v1.w;
        }
    };
    auto storeB = [&](int c, int buf) {
        float f[8];
        #pragma unroll
        for (int j = 0; j < 8; j++) f[j] = pv[j];
        if (FUSEIN) {
            int kg0 = c*32 + 2*kp;
            float a0 = ain[kg0], b0 = bin[kg0];
            float a1 = ain[kg0+1], b1 = bin[kg0+1];
            #pragma unroll
            for (int j = 0; j < 4; j++) f[j]   = gelu_exact(fmaf(a0, f[j],   b0));
            #pragma unroll
            for (int j = 0; j < 4; j++) f[j+4] = gelu_exact(fmaf(a1, f[j+4], b1));
        }
        uint4 u;
        __half2 h;
        h = __floats2half2_rn(f[0], f[4]); u.x = *(uint32_t*)&h;
        h = __floats2half2_rn(f[1], f[5]); u.y = *(uint32_t*)&h;
        h = __floats2half2_rn(f[2], f[6]); u.z = *(uint32_t*)&h;
        h = __floats2half2_rn(f[3], f[7]); u.w = *(uint32_t*)&h;
        ((uint4*)Bs[buf])[kp*16 + (n4 ^ ((kp & 3) << 1))] = u;
    };
    auto stageA = [&](int c, int buf) {
        const uint32_t* src = Aimg + (size_t)c*4096 + t*4;
        uint32_t base = smem_u32(&As[buf][0]);
        #pragma unroll
        for (int j = 0; j < 4; j++)
            cp16(base + (uint32_t)(t + j*256)*16u, src + j*1024);
    };
    auto compute = [&](int buf) {
        uint4 af[4][2];
        #pragma unroll
        for (int mf = 0; mf < 4; mf++)
            #pragma unroll
            for (int bk = 0; bk < 2; bk++)
                af[mf][bk] = As[buf][((wm*4 + mf)*2 + bk)*32 + l];
        uint32_t bf[4][2][2];
        #pragma unroll
        for (int bnl = 0; bnl < 4; bnl++) {
            int n = wn*32 + bnl*8 + g;
            int nsw = n ^ (tq << 3);
            #pragma unroll
            for (int bk = 0; bk < 2; bk++) {
                bf[bnl][bk][0] = Bs[buf][(bk*8 + tq)*64 + nsw];
                bf[bnl][bk][1] = Bs[buf][(bk*8 + tq + 4)*64 + nsw];
            }
        }
        #pragma unroll
        for (int mf = 0; mf < 4; mf++)
            #pragma unroll
            for (int bnl = 0; bnl < 4; bnl++)
                #pragma unroll
                for (int bk = 0; bk < 2; bk++)
                    MMA_F16(acc[mf][bnl], af[mf][bk], bf[bnl][bk][0], bf[bnl][bk][1]);
    };

    // pipeline
    stageB(0);
    stageA(0, 0); cp_commit();
    storeB(0, 0);
    for (int c = 0; c < NC; c++) {
        int buf = c & 1;
        cp_wait0();
        __syncthreads();
        if (c + 1 < NC) { stageB(c + 1); stageA(c + 1, buf ^ 1); cp_commit(); }
        compute(buf);
        if (c + 1 < NC) storeB(c + 1, buf ^ 1);
    }

    // ---- epilogue: bias, store, stats ----
    #pragma unroll
    for (int mf = 0; mf < 4; mf++) {
        int o_lo = wm*64 + mf*16 + g;
        int o_hi = o_lo + 8;
        float bl = bias[b*CO + o_lo];
        float bh = bias[b*CO + o_hi];
        float sl = 0.f, ql = 0.f, sh = 0.f, qh = 0.f;
        #pragma unroll
        for (int bnl = 0; bnl < 4; bnl++) {
            int col = nT + wn*32 + bnl*8 + 2*tq;
            float v0 = acc[mf][bnl][0] + bl;
            float v1 = acc[mf][bnl][1] + bl;
            float v2 = acc[mf][bnl][2] + bh;
            float v3 = acc[mf][bnl][3] + bh;
            if (OUTH) {
                __half2 hlo = __floats2half2_rn(v0, v1);
                __half2 hhi = __floats2half2_rn(v2, v3);
                *(__half2*)(Yh + (size_t)b*CO*NN + (size_t)o_lo*NN + col) = hlo;
                *(__half2*)(Yh + (size_t)b*CO*NN + (size_t)o_hi*NN + col) = hhi;
            } else {
                float2 lo2; lo2.x = v0; lo2.y = v1;
                float2 hi2; hi2.x = v2; hi2.y = v3;
                *(float2*)(Yf + (size_t)b*CO*NN + (size_t)o_lo*NN + col) = lo2;
                *(float2*)(Yf + (size_t)b*CO*NN + (size_t)o_hi*NN + col) = hi2;
            }
            sl += v0 + v1; ql += v0*v0 + v1*v1;
            sh += v2 + v3; qh += v2*v2 + v3*v3;
        }
        #pragma unroll
        for (int off = 1; off <= 2; off <<= 1) {
            sl += __shfl_xor_sync(0xffffffffu, sl, off);
            ql += __shfl_xor_sync(0xffffffffu, ql, off);
            sh += __shfl_xor_sync(0xffffffffu, sh, off);
            qh += __shfl_xor_sync(0xffffffffu, qh, off);
        }
        if (tq == 0) {
            atomicAdd(&redS[o_lo], sl);
            atomicAdd(&redQ[o_lo], ql);
            atomicAdd(&redS[o_hi], sh);
            atomicAdd(&redQ[o_hi], qh);
        }
    }
    __syncthreads();
    atomicAdd(&sumOut[t], redS[t]);
    atomicAdd(&sqOut[t],  redQ[t]);
}

// ---------------- BN scale/shift finalize ----------------
__global__ void bn_finalize(const float* __restrict__ sum, const float* __restrict__ sq,
                            const float* __restrict__ gamma, const float* __restrict__ beta,
                            float* __restrict__ aOut, float* __restrict__ bOut)
{
    int c = threadIdx.x;
    float m = sum[c] * (1.0f/COUNT_BN);
    float v = sq[c]  * (1.0f/COUNT_BN) - m*m;
    float inv = rsqrtf(v + 1e-5f);
    float a = gamma[c] * inv;
    aOut[c] = a;
    bOut[c] = beta[c] - a*m;
}

// ---------------- final: out = gelu(a2[c]*out + b2[c]) in place ----------------
__global__ void final_kernel(float* __restrict__ out)
{
    size_t i4 = (size_t)blockIdx.x * blockDim.x + threadIdx.x;
    size_t total4 = (size_t)BB*CO*NN/4;
    if (i4 >= total4) return;
    float4 v = ((float4*)out)[i4];
    size_t i = i4 * 4;
    int c = (int)((i / NN) % CO);
    float a = d_a2[c], bo = d_b2[c];
    v.x = gelu_exact(fmaf(a, v.x, bo));
    v.y = gelu_exact(fmaf(a, v.y, bo));
    v.z = gelu_exact(fmaf(a, v.z, bo));
    v.w = gelu_exact(fmaf(a, v.w, bo));
    ((float4*)out)[i4] = v;
}

// ---------------- launch ----------------
extern "C" void kernel_launch(void* const* d_in, const int* in_sizes, int n_in,
                              void* d_out, int out_size)
{
    const float* xyz1    = (const float*)d_in[0];
    const float* xyz2    = (const float*)d_in[1];
    const float* points1 = (const float*)d_in[2];
    const float* points2 = (const float*)d_in[3];
    const float* t_embed = (const float*)d_in[4];
    const float* w_t1 = (const float*)d_in[5];
    const float* b_t1 = (const float*)d_in[6];
    const float* w_c1 = (const float*)d_in[7];
    const float* b_c1 = (const float*)d_in[8];
    const float* g1   = (const float*)d_in[9];
    const float* be1  = (const float*)d_in[10];
    const float* w_t2 = (const float*)d_in[11];
    const float* b_t2 = (const float*)d_in[12];
    const float* w_c2 = (const float*)d_in[13];
    const float* b_c2 = (const float*)d_in[14];
    const float* g2   = (const float*)d_in[15];
    const float* be2  = (const float*)d_in[16];
    float* out = (float*)d_out;

    float *p_itp, *p_bias1, *p_bias2;
    float *p_sum1, *p_sq1, *p_sum2, *p_sq2, *p_a1, *p_b1, *p_a2, *p_b2;
    __half *p_y1h, *p_w1i, *p_w2i;
    cudaGetSymbolAddress((void**)&p_itp,   d_itp);
    cudaGetSymbolAddress((void**)&p_y1h,   d_y1h);
    cudaGetSymbolAddress((void**)&p_bias1, d_bias1);
    cudaGetSymbolAddress((void**)&p_bias2, d_bias2);
    cudaGetSymbolAddress((void**)&p_sum1,  d_sum1);
    cudaGetSymbolAddress((void**)&p_sq1,   d_sq1);
    cudaGetSymbolAddress((void**)&p_sum2,  d_sum2);
    cudaGetSymbolAddress((void**)&p_sq2,   d_sq2);
    cudaGetSymbolAddress((void**)&p_a1,    d_a1);
    cudaGetSymbolAddress((void**)&p_b1,    d_b1);
    cudaGetSymbolAddress((void**)&p_a2,    d_a2);
    cudaGetSymbolAddress((void**)&p_b2,    d_b2);
    cudaGetSymbolAddress((void**)&p_w1i,   d_w1img);
    cudaGetSymbolAddress((void**)&p_w2i,   d_w2img);

    prep_kernel<<<BB, 384>>>(t_embed, w_t1, b_t1, w_c1, b_c1, w_t2, b_t2, w_c2, b_c2);
    permA16<<<(CO*CIN + 255)/256, 256>>>(w_c1, p_w1i, CIN);
    permA16<<<(CO*CO  + 255)/256, 256>>>(w_c2, p_w2i, CO);
    transpose_p2<<<dim3(SS/32, C2c/32, BB), dim3(32, 8)>>>(points2);
    top3_kernel<<<dim3(NN/256, BB), 256>>>(xyz1, xyz2);
    interp_kernel<<<dim3(NN/32, BB), 256>>>();

    // Layer 1: y1h = fp16(w_c1 @ [points1; itp] + bias1), stats from fp32 accumulators
    gemm_f16<CIN, false, false, true><<<dim3(NN/64, BB), 256>>>(
        p_w1i, points1, (size_t)C1c*NN, p_itp, (size_t)C2c*NN, C1c,
        (const __half*)nullptr, nullptr, p_y1h,
        p_bias1, nullptr, nullptr, p_sum1, p_sq1);
    bn_finalize<<<1, 256>>>(p_sum1, p_sq1, g1, be1, p_a1, p_b1);

    // Layer 2: out_raw = w_c2 @ gelu(bn1(y1h)) + bias2, stats accumulated
    gemm_f16<CO, true, true, false><<<dim3(NN/64, BB), 256>>>(
        p_w2i, nullptr, 0, nullptr, 0, CO,
        p_y1h, out, nullptr,
        p_bias2, p_a1, p_b1, p_sum2, p_sq2);
    bn_finalize<<<1, 256>>>(p_sum2, p_sq2, g2, be2, p_a2, p_b2);

    final_kernel<<<(unsigned)((BB*CO*NN/4 + 255)/256), 256>>>(out);
}